// round 1
// baseline (speedup 1.0000x reference)
#include <cuda_runtime.h>

#define RELS 3
#define F 128
#define NMAX 50000
#define EMAX 800000

// ---------------- scratch (static device globals; no allocation) ----------------
__device__ float g_XW[(size_t)RELS * NMAX * F];   // [r][n][f]  76.8 MB
__device__ float g_H[(size_t)NMAX * F];           // layer-1 output (and layer-1 agg target)
__device__ float g_NQ[NMAX * RELS];
__device__ float g_NK[NMAX * RELS];
__device__ float g_EX[EMAX];
__device__ float g_DEN[NMAX];
__device__ float g_WQ[2 * RELS * F];              // per-layer wq = w_r @ q
__device__ float g_WK[2 * RELS * F];
__device__ float g_CE[2];                         // per-layer scalar we . e

// ---------------- prep: wq/wk vectors + edge scalar ----------------
__global__ void prep_kernel(const float* __restrict__ w1, const float* __restrict__ q1,
                            const float* __restrict__ k1,
                            const float* __restrict__ w2, const float* __restrict__ q2,
                            const float* __restrict__ k2,
                            const float* __restrict__ we1, const float* __restrict__ e1,
                            const float* __restrict__ we2, const float* __restrict__ e2) {
    int idx = blockIdx.x * blockDim.x + threadIdx.x;
    if (idx < 4 * RELS * F) {
        int which = idx / (RELS * F);       // 0: w1.q1  1: w1.k1  2: w2.q2  3: w2.k2
        int rem   = idx % (RELS * F);       // r*F + i
        const float* w = (which < 2) ? w1 : w2;
        const float* v = (which == 0) ? q1 : (which == 1) ? k1 : (which == 2) ? q2 : k2;
        const float* row = w + (size_t)rem * F;   // w[r][i][:]
        float s = 0.f;
        #pragma unroll 8
        for (int o = 0; o < F; o++) s += row[o] * v[o];
        float* d = (which == 0) ? g_WQ
                 : (which == 1) ? g_WK
                 : (which == 2) ? (g_WQ + RELS * F)
                 : (g_WK + RELS * F);
        d[rem] = s;
    } else if (idx == 4 * RELS * F) {
        float s = 0.f;
        for (int o = 0; o < F; o++) s += we1[o] * e1[o];
        g_CE[0] = s;
    } else if (idx == 4 * RELS * F + 1) {
        float s = 0.f;
        for (int o = 0; o < F; o++) s += we2[o] * e2[o];
        g_CE[1] = s;
    }
}

// ---------------- GEMM: XW[r] = X @ W_r   (M=N, K=128, Nout=128) ----------------
// 128x128 block tile, BK=32, 256 threads, 8x8 per-thread microtile.
#define BM 128
#define BN 128
#define BK 32
#define TM 8
#define TN 8

__global__ __launch_bounds__(256) void gemm_xw_kernel(const float* __restrict__ xin,
                                                      int use_h,
                                                      const float* __restrict__ W,
                                                      int Nn) {
    const float* X = use_h ? g_H : xin;
    int r = blockIdx.y;
    const float* Wr = W + (size_t)r * F * F;
    float* outp = g_XW + (size_t)r * Nn * F;
    int rowBase = blockIdx.x * BM;

    __shared__ float As[BK][BM];
    __shared__ float Bs[BK][BN];

    int tid = threadIdx.x;
    int tx = tid % (BN / TN);   // 0..15 col group
    int ty = tid / (BN / TN);   // 0..15 row group

    float acc[TM][TN];
    #pragma unroll
    for (int i = 0; i < TM; i++)
        #pragma unroll
        for (int j = 0; j < TN; j++) acc[i][j] = 0.f;

    for (int k0 = 0; k0 < F; k0 += BK) {
        // A tile: rows rowBase..+127, cols k0..k0+31 -> As[k][m] (transposed)
        #pragma unroll
        for (int i = 0; i < 4; i++) {
            int idx = tid + i * 256;       // float4 index, 0..1023
            int arow = idx >> 3;           // 8 float4 per row
            int ac4  = idx & 7;
            float4 v = make_float4(0.f, 0.f, 0.f, 0.f);
            int grow = rowBase + arow;
            if (grow < Nn)
                v = *(const float4*)(X + (size_t)grow * F + k0 + ac4 * 4);
            As[ac4 * 4 + 0][arow] = v.x;
            As[ac4 * 4 + 1][arow] = v.y;
            As[ac4 * 4 + 2][arow] = v.z;
            As[ac4 * 4 + 3][arow] = v.w;
        }
        // B tile: Wr rows k0..k0+31, all 128 cols -> Bs[k][n]
        #pragma unroll
        for (int i = 0; i < 4; i++) {
            int idx = tid + i * 256;
            int brow = idx >> 5;           // 32 float4 per row
            int bc4  = idx & 31;
            float4 v = *(const float4*)(Wr + (size_t)(k0 + brow) * F + bc4 * 4);
            *(float4*)&Bs[brow][bc4 * 4] = v;
        }
        __syncthreads();

        #pragma unroll
        for (int k = 0; k < BK; k++) {
            float a[TM], b[TN];
            #pragma unroll
            for (int i = 0; i < TM; i++) a[i] = As[k][ty * TM + i];
            #pragma unroll
            for (int j = 0; j < TN; j++) b[j] = Bs[k][tx * TN + j];
            #pragma unroll
            for (int i = 0; i < TM; i++)
                #pragma unroll
                for (int j = 0; j < TN; j++)
                    acc[i][j] += a[i] * b[j];
        }
        __syncthreads();
    }

    #pragma unroll
    for (int i = 0; i < TM; i++) {
        int grow = rowBase + ty * TM + i;
        if (grow < Nn) {
            #pragma unroll
            for (int j = 0; j < TN; j += 4) {
                float4 v = make_float4(acc[i][j], acc[i][j + 1], acc[i][j + 2], acc[i][j + 3]);
                *(float4*)(outp + (size_t)grow * F + tx * TN + j) = v;
            }
        }
    }
}

// ---------------- per-node attention logits: nq = x . wq[r], nk = x . wk[r] ----------------
__global__ __launch_bounds__(256) void nqnk_kernel(const float* __restrict__ xin,
                                                   int use_h, int layer, int Nn) {
    __shared__ float swq[RELS * F];
    __shared__ float swk[RELS * F];
    const float* X = use_h ? g_H : xin;
    const float* WQ = g_WQ + layer * RELS * F;
    const float* WK = g_WK + layer * RELS * F;
    for (int i = threadIdx.x; i < RELS * F; i += blockDim.x) {
        swq[i] = WQ[i];
        swk[i] = WK[i];
    }
    __syncthreads();

    int warp = (blockIdx.x * blockDim.x + threadIdx.x) >> 5;
    int lane = threadIdx.x & 31;
    if (warp >= Nn) return;

    const float* xr = X + (size_t)warp * F;
    float x0 = xr[lane], x1 = xr[lane + 32], x2 = xr[lane + 64], x3 = xr[lane + 96];

    #pragma unroll
    for (int r = 0; r < RELS; r++) {
        const float* wq = swq + r * F;
        const float* wk = swk + r * F;
        float sq = x0 * wq[lane] + x1 * wq[lane + 32] + x2 * wq[lane + 64] + x3 * wq[lane + 96];
        float sk = x0 * wk[lane] + x1 * wk[lane + 32] + x2 * wk[lane + 64] + x3 * wk[lane + 96];
        #pragma unroll
        for (int off = 16; off; off >>= 1) {
            sq += __shfl_down_sync(0xffffffffu, sq, off);
            sk += __shfl_down_sync(0xffffffffu, sk, off);
        }
        if (lane == 0) {
            g_NQ[warp * RELS + r] = sq;
            g_NK[warp * RELS + r] = sk;
        }
    }
}

// ---------------- zero helpers ----------------
__global__ void zero_den_kernel(int Nn) {
    int i = blockIdx.x * blockDim.x + threadIdx.x;
    if (i < Nn) g_DEN[i] = 0.f;
}
__global__ void zero_h_kernel(size_t n) {
    size_t i = (size_t)blockIdx.x * blockDim.x + threadIdx.x;
    if (i < n) g_H[i] = 0.f;
}
__global__ void zero_buf_kernel(float* __restrict__ p, size_t n) {
    size_t i = (size_t)blockIdx.x * blockDim.x + threadIdx.x;
    if (i < n) p[i] = 0.f;
}

// ---------------- edge pass 1: alpha -> exp, accumulate denominator ----------------
__global__ __launch_bounds__(256) void edge1_kernel(const int* __restrict__ src,
                                                    const int* __restrict__ dst,
                                                    const int* __restrict__ et,
                                                    const float* __restrict__ ea,
                                                    int layer, int Ecnt) {
    int e = blockIdx.x * blockDim.x + threadIdx.x;
    if (e >= Ecnt) return;
    int s = src[e], d = dst[e], t = et[e];
    float a = g_NQ[d * RELS + t] + g_NK[s * RELS + t] + g_CE[layer] * ea[e];
    a = (a > 0.f) ? a : 0.2f * a;            // leaky_relu 0.2
    float ex = expf(a);                       // softmax shift-invariant; alpha is O(10)
    g_EX[e] = ex;
    atomicAdd(&g_DEN[d], ex);
}

// ---------------- edge pass 2: gather xw[src,etype], scale by attn, scatter-add to dst ----------------
__global__ __launch_bounds__(256) void edge2_kernel(const int* __restrict__ src,
                                                    const int* __restrict__ dst,
                                                    const int* __restrict__ et,
                                                    float* __restrict__ dout,
                                                    int use_h, int Ecnt, int Nn) {
    int warp = (blockIdx.x * blockDim.x + threadIdx.x) >> 5;
    int lane = threadIdx.x & 31;
    if (warp >= Ecnt) return;
    float* outp = use_h ? g_H : dout;
    int s = src[warp], d = dst[warp], t = et[warp];
    float attn = g_EX[warp] / (g_DEN[d] + 1e-16f);
    const float4* row = (const float4*)(g_XW + ((size_t)t * Nn + s) * F);
    float4 v = row[lane];
    float* ob = outp + (size_t)d * F + lane * 4;
    atomicAdd(ob + 0, attn * v.x);
    atomicAdd(ob + 1, attn * v.y);
    atomicAdd(ob + 2, attn * v.z);
    atomicAdd(ob + 3, attn * v.w);
}

// ---------------- epilogue: bias (+ optional relu), in place ----------------
__global__ void postact_kernel(float* __restrict__ dout, int use_h,
                               const float* __restrict__ bias, int relu, size_t n) {
    size_t i = (size_t)blockIdx.x * blockDim.x + threadIdx.x;
    if (i >= n) return;
    float* buf = use_h ? g_H : dout;
    float v = buf[i] + bias[i & (F - 1)];
    if (relu) v = v > 0.f ? v : 0.f;
    buf[i] = v;
}

// ---------------- launch ----------------
extern "C" void kernel_launch(void* const* d_in, const int* in_sizes, int n_in,
                              void* d_out, int out_size) {
    const float* x   = (const float*)d_in[0];
    const int*   ei  = (const int*)d_in[1];
    const int*   et  = (const int*)d_in[2];
    const float* ea  = (const float*)d_in[3];
    const float* w1  = (const float*)d_in[4];
    const float* q1  = (const float*)d_in[5];
    const float* k1  = (const float*)d_in[6];
    const float* e1  = (const float*)d_in[7];
    const float* we1 = (const float*)d_in[8];
    const float* b1  = (const float*)d_in[9];
    const float* w2  = (const float*)d_in[10];
    const float* q2  = (const float*)d_in[11];
    const float* k2  = (const float*)d_in[12];
    const float* e2  = (const float*)d_in[13];
    const float* we2 = (const float*)d_in[14];
    const float* b2  = (const float*)d_in[15];

    int Nn = in_sizes[0] / F;
    int Ecnt = in_sizes[2];
    const int* srcp = ei;
    const int* dstp = ei + Ecnt;
    float* outp = (float*)d_out;

    size_t nelems = (size_t)Nn * F;

    prep_kernel<<<(4 * RELS * F + 2 + 255) / 256, 256>>>(w1, q1, k1, w2, q2, k2,
                                                         we1, e1, we2, e2);

    dim3 gemmGrid((Nn + BM - 1) / BM, RELS);
    int nqnkBlocks = (Nn + 7) / 8;               // 8 warps/block, warp per node
    int edge1Blocks = (Ecnt + 255) / 256;
    int edge2Blocks = (Ecnt + 7) / 8;            // 8 warps/block, warp per edge
    int elemBlocks = (int)((nelems + 255) / 256);

    // ----- layer 1 -----
    gemm_xw_kernel<<<gemmGrid, 256>>>(x, 0, w1, Nn);
    nqnk_kernel<<<nqnkBlocks, 256>>>(x, 0, 0, Nn);
    zero_den_kernel<<<(Nn + 255) / 256, 256>>>(Nn);
    zero_h_kernel<<<elemBlocks, 256>>>(nelems);
    edge1_kernel<<<edge1Blocks, 256>>>(srcp, dstp, et, ea, 0, Ecnt);
    edge2_kernel<<<edge2Blocks, 256>>>(srcp, dstp, et, outp, 1, Ecnt, Nn);
    postact_kernel<<<elemBlocks, 256>>>(outp, 1, b1, 1, nelems);   // relu -> g_H

    // ----- layer 2 -----
    gemm_xw_kernel<<<gemmGrid, 256>>>(x, 1, w2, Nn);
    nqnk_kernel<<<nqnkBlocks, 256>>>(x, 1, 1, Nn);
    zero_den_kernel<<<(Nn + 255) / 256, 256>>>(Nn);
    zero_buf_kernel<<<elemBlocks, 256>>>(outp, nelems);
    edge1_kernel<<<edge1Blocks, 256>>>(srcp, dstp, et, ea, 1, Ecnt);
    edge2_kernel<<<edge2Blocks, 256>>>(srcp, dstp, et, outp, 0, Ecnt, Nn);
    postact_kernel<<<elemBlocks, 256>>>(outp, 0, b2, 0, nelems);
}

// round 2
// speedup vs baseline: 1.0036x; 1.0036x over previous
#include <cuda_runtime.h>

#define RELS 3
#define F 128
#define NMAX 50000
#define EMAX 800000

// ---------------- scratch (static device globals; no allocation) ----------------
__device__ float g_XW[(size_t)RELS * NMAX * F];   // [r][n][f]  76.8 MB
__device__ float g_H[(size_t)NMAX * F];           // layer-1 output (and layer-1 agg target)
__device__ float g_NQ[NMAX * RELS];
__device__ float g_NK[NMAX * RELS];
__device__ float g_EX[EMAX];
__device__ float g_DEN[NMAX];
__device__ float g_WQ[2 * RELS * F];              // per-layer wq = w_r @ q
__device__ float g_WK[2 * RELS * F];
__device__ float g_CE[2];                         // per-layer scalar we . e

// ---------------- prep: wq/wk vectors + edge scalar ----------------
__global__ void prep_kernel(const float* __restrict__ w1, const float* __restrict__ q1,
                            const float* __restrict__ k1,
                            const float* __restrict__ w2, const float* __restrict__ q2,
                            const float* __restrict__ k2,
                            const float* __restrict__ we1, const float* __restrict__ e1,
                            const float* __restrict__ we2, const float* __restrict__ e2) {
    int idx = blockIdx.x * blockDim.x + threadIdx.x;
    if (idx < 4 * RELS * F) {
        int which = idx / (RELS * F);       // 0: w1.q1  1: w1.k1  2: w2.q2  3: w2.k2
        int rem   = idx % (RELS * F);       // r*F + i
        const float* w = (which < 2) ? w1 : w2;
        const float* v = (which == 0) ? q1 : (which == 1) ? k1 : (which == 2) ? q2 : k2;
        const float* row = w + (size_t)rem * F;   // w[r][i][:]
        float s = 0.f;
        #pragma unroll 8
        for (int o = 0; o < F; o++) s += row[o] * v[o];
        float* d = (which == 0) ? g_WQ
                 : (which == 1) ? g_WK
                 : (which == 2) ? (g_WQ + RELS * F)
                 : (g_WK + RELS * F);
        d[rem] = s;
    } else if (idx == 4 * RELS * F) {
        float s = 0.f;
        for (int o = 0; o < F; o++) s += we1[o] * e1[o];
        g_CE[0] = s;
    } else if (idx == 4 * RELS * F + 1) {
        float s = 0.f;
        for (int o = 0; o < F; o++) s += we2[o] * e2[o];
        g_CE[1] = s;
    }
}

// ---------------- GEMM: XW[r] = X @ W_r   (M=N, K=128, Nout=128) ----------------
// 128x128 block tile, BK=32, 256 threads, 8x8 per-thread microtile.
#define BM 128
#define BN 128
#define BK 32
#define TM 8
#define TN 8

__global__ __launch_bounds__(256) void gemm_xw_kernel(const float* __restrict__ xin,
                                                      int use_h,
                                                      const float* __restrict__ W,
                                                      int Nn) {
    const float* X = use_h ? g_H : xin;
    int r = blockIdx.y;
    const float* Wr = W + (size_t)r * F * F;
    float* outp = g_XW + (size_t)r * Nn * F;
    int rowBase = blockIdx.x * BM;

    __shared__ float As[BK][BM];
    __shared__ float Bs[BK][BN];

    int tid = threadIdx.x;
    int tx = tid % (BN / TN);   // 0..15 col group
    int ty = tid / (BN / TN);   // 0..15 row group

    float acc[TM][TN];
    #pragma unroll
    for (int i = 0; i < TM; i++)
        #pragma unroll
        for (int j = 0; j < TN; j++) acc[i][j] = 0.f;

    for (int k0 = 0; k0 < F; k0 += BK) {
        // A tile: rows rowBase..+127, cols k0..k0+31 -> As[k][m] (transposed)
        #pragma unroll
        for (int i = 0; i < 4; i++) {
            int idx = tid + i * 256;       // float4 index, 0..1023
            int arow = idx >> 3;           // 8 float4 per row
            int ac4  = idx & 7;
            float4 v = make_float4(0.f, 0.f, 0.f, 0.f);
            int grow = rowBase + arow;
            if (grow < Nn)
                v = *(const float4*)(X + (size_t)grow * F + k0 + ac4 * 4);
            As[ac4 * 4 + 0][arow] = v.x;
            As[ac4 * 4 + 1][arow] = v.y;
            As[ac4 * 4 + 2][arow] = v.z;
            As[ac4 * 4 + 3][arow] = v.w;
        }
        // B tile: Wr rows k0..k0+31, all 128 cols -> Bs[k][n]
        #pragma unroll
        for (int i = 0; i < 4; i++) {
            int idx = tid + i * 256;
            int brow = idx >> 5;           // 32 float4 per row
            int bc4  = idx & 31;
            float4 v = *(const float4*)(Wr + (size_t)(k0 + brow) * F + bc4 * 4);
            *(float4*)&Bs[brow][bc4 * 4] = v;
        }
        __syncthreads();

        #pragma unroll
        for (int k = 0; k < BK; k++) {
            float a[TM], b[TN];
            #pragma unroll
            for (int i = 0; i < TM; i++) a[i] = As[k][ty * TM + i];
            #pragma unroll
            for (int j = 0; j < TN; j++) b[j] = Bs[k][tx * TN + j];
            #pragma unroll
            for (int i = 0; i < TM; i++)
                #pragma unroll
                for (int j = 0; j < TN; j++)
                    acc[i][j] += a[i] * b[j];
        }
        __syncthreads();
    }

    #pragma unroll
    for (int i = 0; i < TM; i++) {
        int grow = rowBase + ty * TM + i;
        if (grow < Nn) {
            #pragma unroll
            for (int j = 0; j < TN; j += 4) {
                float4 v = make_float4(acc[i][j], acc[i][j + 1], acc[i][j + 2], acc[i][j + 3]);
                *(float4*)(outp + (size_t)grow * F + tx * TN + j) = v;
            }
        }
    }
}

// ---------------- per-node attention logits: nq = x . wq[r], nk = x . wk[r] ----------------
__global__ __launch_bounds__(256) void nqnk_kernel(const float* __restrict__ xin,
                                                   int use_h, int layer, int Nn) {
    __shared__ float swq[RELS * F];
    __shared__ float swk[RELS * F];
    const float* X = use_h ? g_H : xin;
    const float* WQ = g_WQ + layer * RELS * F;
    const float* WK = g_WK + layer * RELS * F;
    for (int i = threadIdx.x; i < RELS * F; i += blockDim.x) {
        swq[i] = WQ[i];
        swk[i] = WK[i];
    }
    __syncthreads();

    int warp = (blockIdx.x * blockDim.x + threadIdx.x) >> 5;
    int lane = threadIdx.x & 31;
    if (warp >= Nn) return;

    const float* xr = X + (size_t)warp * F;
    float x0 = xr[lane], x1 = xr[lane + 32], x2 = xr[lane + 64], x3 = xr[lane + 96];

    #pragma unroll
    for (int r = 0; r < RELS; r++) {
        const float* wq = swq + r * F;
        const float* wk = swk + r * F;
        float sq = x0 * wq[lane] + x1 * wq[lane + 32] + x2 * wq[lane + 64] + x3 * wq[lane + 96];
        float sk = x0 * wk[lane] + x1 * wk[lane + 32] + x2 * wk[lane + 64] + x3 * wk[lane + 96];
        #pragma unroll
        for (int off = 16; off; off >>= 1) {
            sq += __shfl_down_sync(0xffffffffu, sq, off);
            sk += __shfl_down_sync(0xffffffffu, sk, off);
        }
        if (lane == 0) {
            g_NQ[warp * RELS + r] = sq;
            g_NK[warp * RELS + r] = sk;
        }
    }
}

// ---------------- zero helpers ----------------
__global__ void zero_den_kernel(int Nn) {
    int i = blockIdx.x * blockDim.x + threadIdx.x;
    if (i < Nn) g_DEN[i] = 0.f;
}
__global__ void zero_h_kernel(size_t n) {
    size_t i = (size_t)blockIdx.x * blockDim.x + threadIdx.x;
    if (i < n) g_H[i] = 0.f;
}
__global__ void zero_buf_kernel(float* __restrict__ p, size_t n) {
    size_t i = (size_t)blockIdx.x * blockDim.x + threadIdx.x;
    if (i < n) p[i] = 0.f;
}

// ---------------- edge pass 1: alpha -> exp, accumulate denominator ----------------
__global__ __launch_bounds__(256) void edge1_kernel(const int* __restrict__ src,
                                                    const int* __restrict__ dst,
                                                    const int* __restrict__ et,
                                                    const float* __restrict__ ea,
                                                    int layer, int Ecnt) {
    int e = blockIdx.x * blockDim.x + threadIdx.x;
    if (e >= Ecnt) return;
    int s = src[e], d = dst[e], t = et[e];
    float a = g_NQ[d * RELS + t] + g_NK[s * RELS + t] + g_CE[layer] * ea[e];
    a = (a > 0.f) ? a : 0.2f * a;            // leaky_relu 0.2
    float ex = expf(a);                       // softmax shift-invariant; alpha is O(10)
    g_EX[e] = ex;
    atomicAdd(&g_DEN[d], ex);
}

// ---------------- edge pass 2: gather xw[src,etype], scale by attn, scatter-add to dst ----------------
__global__ __launch_bounds__(256) void edge2_kernel(const int* __restrict__ src,
                                                    const int* __restrict__ dst,
                                                    const int* __restrict__ et,
                                                    float* __restrict__ dout,
                                                    int use_h, int Ecnt, int Nn) {
    int warp = (blockIdx.x * blockDim.x + threadIdx.x) >> 5;
    int lane = threadIdx.x & 31;
    if (warp >= Ecnt) return;
    float* outp = use_h ? g_H : dout;
    int s = src[warp], d = dst[warp], t = et[warp];
    float attn = g_EX[warp] / (g_DEN[d] + 1e-16f);
    const float4* row = (const float4*)(g_XW + ((size_t)t * Nn + s) * F);
    float4 v = row[lane];
    float* ob = outp + (size_t)d * F + lane * 4;
    atomicAdd(ob + 0, attn * v.x);
    atomicAdd(ob + 1, attn * v.y);
    atomicAdd(ob + 2, attn * v.z);
    atomicAdd(ob + 3, attn * v.w);
}

// ---------------- epilogue: bias (+ optional relu), in place ----------------
__global__ void postact_kernel(float* __restrict__ dout, int use_h,
                               const float* __restrict__ bias, int relu, size_t n) {
    size_t i = (size_t)blockIdx.x * blockDim.x + threadIdx.x;
    if (i >= n) return;
    float* buf = use_h ? g_H : dout;
    float v = buf[i] + bias[i & (F - 1)];
    if (relu) v = v > 0.f ? v : 0.f;
    buf[i] = v;
}

// ---------------- launch ----------------
extern "C" void kernel_launch(void* const* d_in, const int* in_sizes, int n_in,
                              void* d_out, int out_size) {
    const float* x   = (const float*)d_in[0];
    const int*   ei  = (const int*)d_in[1];
    const int*   et  = (const int*)d_in[2];
    const float* ea  = (const float*)d_in[3];
    const float* w1  = (const float*)d_in[4];
    const float* q1  = (const float*)d_in[5];
    const float* k1  = (const float*)d_in[6];
    const float* e1  = (const float*)d_in[7];
    const float* we1 = (const float*)d_in[8];
    const float* b1  = (const float*)d_in[9];
    const float* w2  = (const float*)d_in[10];
    const float* q2  = (const float*)d_in[11];
    const float* k2  = (const float*)d_in[12];
    const float* e2  = (const float*)d_in[13];
    const float* we2 = (const float*)d_in[14];
    const float* b2  = (const float*)d_in[15];

    int Nn = in_sizes[0] / F;
    int Ecnt = in_sizes[2];
    const int* srcp = ei;
    const int* dstp = ei + Ecnt;
    float* outp = (float*)d_out;

    size_t nelems = (size_t)Nn * F;

    prep_kernel<<<(4 * RELS * F + 2 + 255) / 256, 256>>>(w1, q1, k1, w2, q2, k2,
                                                         we1, e1, we2, e2);

    dim3 gemmGrid((Nn + BM - 1) / BM, RELS);
    int nqnkBlocks = (Nn + 7) / 8;               // 8 warps/block, warp per node
    int edge1Blocks = (Ecnt + 255) / 256;
    int edge2Blocks = (Ecnt + 7) / 8;            // 8 warps/block, warp per edge
    int elemBlocks = (int)((nelems + 255) / 256);

    // ----- layer 1 -----
    gemm_xw_kernel<<<gemmGrid, 256>>>(x, 0, w1, Nn);
    nqnk_kernel<<<nqnkBlocks, 256>>>(x, 0, 0, Nn);
    zero_den_kernel<<<(Nn + 255) / 256, 256>>>(Nn);
    zero_h_kernel<<<elemBlocks, 256>>>(nelems);
    edge1_kernel<<<edge1Blocks, 256>>>(srcp, dstp, et, ea, 0, Ecnt);
    edge2_kernel<<<edge2Blocks, 256>>>(srcp, dstp, et, outp, 1, Ecnt, Nn);
    postact_kernel<<<elemBlocks, 256>>>(outp, 1, b1, 1, nelems);   // relu -> g_H

    // ----- layer 2 -----
    gemm_xw_kernel<<<gemmGrid, 256>>>(x, 1, w2, Nn);
    nqnk_kernel<<<nqnkBlocks, 256>>>(x, 1, 1, Nn);
    zero_den_kernel<<<(Nn + 255) / 256, 256>>>(Nn);
    zero_buf_kernel<<<elemBlocks, 256>>>(outp, nelems);
    edge1_kernel<<<edge1Blocks, 256>>>(srcp, dstp, et, ea, 1, Ecnt);
    edge2_kernel<<<edge2Blocks, 256>>>(srcp, dstp, et, outp, 0, Ecnt, Nn);
    postact_kernel<<<elemBlocks, 256>>>(outp, 0, b2, 0, nelems);
}

// round 3
// speedup vs baseline: 1.8148x; 1.8083x over previous
#include <cuda_runtime.h>

#define RELS 3
#define F 128
#define NMAX 50000
#define EMAX 800000

// ---------------- scratch (static device globals; no allocation) ----------------
__device__ float g_XW[(size_t)RELS * NMAX * F];   // [r][n][f]  76.8 MB
__device__ float g_H[(size_t)NMAX * F];           // layer-1 output
__device__ float g_NQ[NMAX * RELS];
__device__ float g_NK[NMAX * RELS];
__device__ float g_EX[EMAX];
__device__ float g_WQ[2 * RELS * F];              // per-layer wq = w_r @ q
__device__ float g_WK[2 * RELS * F];
__device__ float g_CE[2];                         // per-layer scalar we . e
// CSR scratch
__device__ int   g_CNT[NMAX];                     // histogram / scatter cursor
__device__ int   g_ROWPTR[NMAX + 1];
__device__ int   g_PART[NMAX];                    // per-elem exclusive scan (within block)
__device__ int   g_BSUM[1024];                    // per-block sums
__device__ int   g_NKIDX[EMAX];                   // sorted: src*RELS + et
__device__ int   g_ROWIDX[EMAX];                  // sorted: et*Nn + src
__device__ float g_SEA[EMAX];                     // sorted: edge_attr

// ---------------- prep: wq/wk vectors + edge scalar ----------------
__global__ void prep_kernel(const float* __restrict__ w1, const float* __restrict__ q1,
                            const float* __restrict__ k1,
                            const float* __restrict__ w2, const float* __restrict__ q2,
                            const float* __restrict__ k2,
                            const float* __restrict__ we1, const float* __restrict__ e1,
                            const float* __restrict__ we2, const float* __restrict__ e2) {
    int idx = blockIdx.x * blockDim.x + threadIdx.x;
    if (idx < 4 * RELS * F) {
        int which = idx / (RELS * F);
        int rem   = idx % (RELS * F);
        const float* w = (which < 2) ? w1 : w2;
        const float* v = (which == 0) ? q1 : (which == 1) ? k1 : (which == 2) ? q2 : k2;
        const float* row = w + (size_t)rem * F;
        float s = 0.f;
        #pragma unroll 8
        for (int o = 0; o < F; o++) s += row[o] * v[o];
        float* d = (which == 0) ? g_WQ
                 : (which == 1) ? g_WK
                 : (which == 2) ? (g_WQ + RELS * F)
                 : (g_WK + RELS * F);
        d[rem] = s;
    } else if (idx == 4 * RELS * F) {
        float s = 0.f;
        for (int o = 0; o < F; o++) s += we1[o] * e1[o];
        g_CE[0] = s;
    } else if (idx == 4 * RELS * F + 1) {
        float s = 0.f;
        for (int o = 0; o < F; o++) s += we2[o] * e2[o];
        g_CE[1] = s;
    }
}

// ---------------- CSR build ----------------
__global__ void zero_cnt_kernel(int Nn) {
    int i = blockIdx.x * blockDim.x + threadIdx.x;
    if (i < Nn) g_CNT[i] = 0;
}

__global__ void hist_kernel(const int* __restrict__ dst, int Ecnt) {
    int e = blockIdx.x * blockDim.x + threadIdx.x;
    if (e < Ecnt) atomicAdd(&g_CNT[dst[e]], 1);
}

// per-block exclusive scan of counts (256/block); block sum out
__global__ void scan1_kernel(int Nn) {
    __shared__ int sh[256];
    int i = blockIdx.x * 256 + threadIdx.x;
    int v = (i < Nn) ? g_CNT[i] : 0;
    sh[threadIdx.x] = v;
    __syncthreads();
    #pragma unroll
    for (int off = 1; off < 256; off <<= 1) {
        int t = (threadIdx.x >= off) ? sh[threadIdx.x - off] : 0;
        __syncthreads();
        sh[threadIdx.x] += t;
        __syncthreads();
    }
    if (i < Nn) g_PART[i] = sh[threadIdx.x] - v;   // exclusive
    if (threadIdx.x == 255) g_BSUM[blockIdx.x] = sh[255];
}

// single-block exclusive scan of block sums (nb <= 1024)
__global__ void scan2_kernel(int nb) {
    __shared__ int sh[1024];
    int v = (threadIdx.x < nb) ? g_BSUM[threadIdx.x] : 0;
    sh[threadIdx.x] = v;
    __syncthreads();
    #pragma unroll
    for (int off = 1; off < 1024; off <<= 1) {
        int t = (threadIdx.x >= off) ? sh[threadIdx.x - off] : 0;
        __syncthreads();
        sh[threadIdx.x] += t;
        __syncthreads();
    }
    if (threadIdx.x < nb) g_BSUM[threadIdx.x] = sh[threadIdx.x] - v;  // exclusive
}

__global__ void scan3_kernel(int Nn, int Ecnt) {
    int i = blockIdx.x * blockDim.x + threadIdx.x;
    if (i < Nn) {
        g_ROWPTR[i] = g_PART[i] + g_BSUM[i >> 8];
        g_CNT[i] = 0;                                // reset as cursor
    }
    if (i == Nn) g_ROWPTR[Nn] = Ecnt;
}

__global__ void scatter_kernel(const int* __restrict__ src, const int* __restrict__ dst,
                               const int* __restrict__ et, const float* __restrict__ ea,
                               int Ecnt, int Nn) {
    int e = blockIdx.x * blockDim.x + threadIdx.x;
    if (e >= Ecnt) return;
    int d = dst[e];
    int pos = g_ROWPTR[d] + atomicAdd(&g_CNT[d], 1);
    int s = src[e], t = et[e];
    g_NKIDX[pos]  = s * RELS + t;
    g_ROWIDX[pos] = t * Nn + s;
    g_SEA[pos]    = ea[e];
}

// ---------------- GEMM: XW[r] = X @ W_r ----------------
#define BM 128
#define BN 128
#define BK 32
#define TM 8
#define TN 8

__global__ __launch_bounds__(256) void gemm_xw_kernel(const float* __restrict__ xin,
                                                      int use_h,
                                                      const float* __restrict__ W,
                                                      int Nn) {
    const float* X = use_h ? g_H : xin;
    int r = blockIdx.y;
    const float* Wr = W + (size_t)r * F * F;
    float* outp = g_XW + (size_t)r * Nn * F;
    int rowBase = blockIdx.x * BM;

    __shared__ float As[BK][BM];
    __shared__ float Bs[BK][BN];

    int tid = threadIdx.x;
    int tx = tid % (BN / TN);
    int ty = tid / (BN / TN);

    float acc[TM][TN];
    #pragma unroll
    for (int i = 0; i < TM; i++)
        #pragma unroll
        for (int j = 0; j < TN; j++) acc[i][j] = 0.f;

    for (int k0 = 0; k0 < F; k0 += BK) {
        #pragma unroll
        for (int i = 0; i < 4; i++) {
            int idx = tid + i * 256;
            int arow = idx >> 3;
            int ac4  = idx & 7;
            float4 v = make_float4(0.f, 0.f, 0.f, 0.f);
            int grow = rowBase + arow;
            if (grow < Nn)
                v = *(const float4*)(X + (size_t)grow * F + k0 + ac4 * 4);
            As[ac4 * 4 + 0][arow] = v.x;
            As[ac4 * 4 + 1][arow] = v.y;
            As[ac4 * 4 + 2][arow] = v.z;
            As[ac4 * 4 + 3][arow] = v.w;
        }
        #pragma unroll
        for (int i = 0; i < 4; i++) {
            int idx = tid + i * 256;
            int brow = idx >> 5;
            int bc4  = idx & 31;
            float4 v = *(const float4*)(Wr + (size_t)(k0 + brow) * F + bc4 * 4);
            *(float4*)&Bs[brow][bc4 * 4] = v;
        }
        __syncthreads();

        #pragma unroll
        for (int k = 0; k < BK; k++) {
            float a[TM], b[TN];
            #pragma unroll
            for (int i = 0; i < TM; i++) a[i] = As[k][ty * TM + i];
            #pragma unroll
            for (int j = 0; j < TN; j++) b[j] = Bs[k][tx * TN + j];
            #pragma unroll
            for (int i = 0; i < TM; i++)
                #pragma unroll
                for (int j = 0; j < TN; j++)
                    acc[i][j] += a[i] * b[j];
        }
        __syncthreads();
    }

    #pragma unroll
    for (int i = 0; i < TM; i++) {
        int grow = rowBase + ty * TM + i;
        if (grow < Nn) {
            #pragma unroll
            for (int j = 0; j < TN; j += 4) {
                float4 v = make_float4(acc[i][j], acc[i][j + 1], acc[i][j + 2], acc[i][j + 3]);
                *(float4*)(outp + (size_t)grow * F + tx * TN + j) = v;
            }
        }
    }
}

// ---------------- per-node attention logits ----------------
__global__ __launch_bounds__(256) void nqnk_kernel(const float* __restrict__ xin,
                                                   int use_h, int layer, int Nn) {
    __shared__ float swq[RELS * F];
    __shared__ float swk[RELS * F];
    const float* X = use_h ? g_H : xin;
    const float* WQ = g_WQ + layer * RELS * F;
    const float* WK = g_WK + layer * RELS * F;
    for (int i = threadIdx.x; i < RELS * F; i += blockDim.x) {
        swq[i] = WQ[i];
        swk[i] = WK[i];
    }
    __syncthreads();

    int warp = (blockIdx.x * blockDim.x + threadIdx.x) >> 5;
    int lane = threadIdx.x & 31;
    if (warp >= Nn) return;

    const float* xr = X + (size_t)warp * F;
    float x0 = xr[lane], x1 = xr[lane + 32], x2 = xr[lane + 64], x3 = xr[lane + 96];

    #pragma unroll
    for (int r = 0; r < RELS; r++) {
        const float* wq = swq + r * F;
        const float* wk = swk + r * F;
        float sq = x0 * wq[lane] + x1 * wq[lane + 32] + x2 * wq[lane + 64] + x3 * wq[lane + 96];
        float sk = x0 * wk[lane] + x1 * wk[lane + 32] + x2 * wk[lane + 64] + x3 * wk[lane + 96];
        #pragma unroll
        for (int off = 16; off; off >>= 1) {
            sq += __shfl_down_sync(0xffffffffu, sq, off);
            sk += __shfl_down_sync(0xffffffffu, sk, off);
        }
        if (lane == 0) {
            g_NQ[warp * RELS + r] = sq;
            g_NK[warp * RELS + r] = sk;
        }
    }
}

// ---------------- fused softmax + aggregate + bias(+relu), warp per dst node ----------------
__global__ __launch_bounds__(256) void fused_agg_kernel(float* __restrict__ outp,
                                                        const float* __restrict__ bias,
                                                        int layer, int relu, int Nn) {
    int node = (blockIdx.x * blockDim.x + threadIdx.x) >> 5;
    int lane = threadIdx.x & 31;
    if (node >= Nn) return;

    int start = g_ROWPTR[node];
    int end   = g_ROWPTR[node + 1];
    float ce  = g_CE[layer];
    float nq0 = g_NQ[node * RELS + 0];
    float nq1 = g_NQ[node * RELS + 1];
    float nq2 = g_NQ[node * RELS + 2];

    // phase 1: lane-parallel exp + denominator
    float denom = 0.f;
    for (int i = start + lane; i < end; i += 32) {
        int nkidx = g_NKIDX[i];
        int t = nkidx - (nkidx / RELS) * RELS;   // nkidx % 3
        float nq = (t == 0) ? nq0 : (t == 1) ? nq1 : nq2;
        float a = nq + g_NK[nkidx] + ce * g_SEA[i];
        a = (a > 0.f) ? a : 0.2f * a;            // leaky_relu 0.2
        float ex = expf(a);                      // softmax shift-invariant; alpha is O(10)
        g_EX[i] = ex;
        denom += ex;
    }
    #pragma unroll
    for (int off = 16; off; off >>= 1)
        denom += __shfl_xor_sync(0xffffffffu, denom, off);
    float inv = 1.f / (denom + 1e-16f);

    // phase 2: warp-per-edge, lanes over features (128f = float4/lane)
    float4 acc = make_float4(0.f, 0.f, 0.f, 0.f);
    int i = start;
    for (; i + 1 < end; i += 2) {
        float at0 = g_EX[i] * inv;
        float at1 = g_EX[i + 1] * inv;
        const float4* r0 = (const float4*)(g_XW + (size_t)g_ROWIDX[i] * F);
        const float4* r1 = (const float4*)(g_XW + (size_t)g_ROWIDX[i + 1] * F);
        float4 v0 = r0[lane];
        float4 v1 = r1[lane];
        acc.x += at0 * v0.x + at1 * v1.x;
        acc.y += at0 * v0.y + at1 * v1.y;
        acc.z += at0 * v0.z + at1 * v1.z;
        acc.w += at0 * v0.w + at1 * v1.w;
    }
    if (i < end) {
        float at = g_EX[i] * inv;
        const float4* r0 = (const float4*)(g_XW + (size_t)g_ROWIDX[i] * F);
        float4 v = r0[lane];
        acc.x += at * v.x;
        acc.y += at * v.y;
        acc.z += at * v.z;
        acc.w += at * v.w;
    }

    const float4 b = *(const float4*)(bias + lane * 4);
    acc.x += b.x; acc.y += b.y; acc.z += b.z; acc.w += b.w;
    if (relu) {
        acc.x = acc.x > 0.f ? acc.x : 0.f;
        acc.y = acc.y > 0.f ? acc.y : 0.f;
        acc.z = acc.z > 0.f ? acc.z : 0.f;
        acc.w = acc.w > 0.f ? acc.w : 0.f;
    }
    *(float4*)(outp + (size_t)node * F + lane * 4) = acc;
}

// ---------------- launch ----------------
extern "C" void kernel_launch(void* const* d_in, const int* in_sizes, int n_in,
                              void* d_out, int out_size) {
    const float* x   = (const float*)d_in[0];
    const int*   ei  = (const int*)d_in[1];
    const int*   et  = (const int*)d_in[2];
    const float* ea  = (const float*)d_in[3];
    const float* w1  = (const float*)d_in[4];
    const float* q1  = (const float*)d_in[5];
    const float* k1  = (const float*)d_in[6];
    const float* e1  = (const float*)d_in[7];
    const float* we1 = (const float*)d_in[8];
    const float* b1  = (const float*)d_in[9];
    const float* w2  = (const float*)d_in[10];
    const float* q2  = (const float*)d_in[11];
    const float* k2  = (const float*)d_in[12];
    const float* e2  = (const float*)d_in[13];
    const float* we2 = (const float*)d_in[14];
    const float* b2  = (const float*)d_in[15];

    int Nn = in_sizes[0] / F;
    int Ecnt = in_sizes[2];
    const int* srcp = ei;
    const int* dstp = ei + Ecnt;
    float* outp = (float*)d_out;

    float* g_H_ptr = nullptr;   // resolved by kernels via device globals

    int nodeBlocks  = (Nn + 255) / 256;
    int edgeBlocks  = (Ecnt + 255) / 256;
    int scanBlocks  = (Nn + 255) / 256;       // 256 elems per block
    dim3 gemmGrid((Nn + BM - 1) / BM, RELS);
    int nqnkBlocks  = (Nn + 7) / 8;
    int warpNodeBlk = (Nn + 7) / 8;           // 8 warps/block

    prep_kernel<<<(4 * RELS * F + 2 + 255) / 256, 256>>>(w1, q1, k1, w2, q2, k2,
                                                         we1, e1, we2, e2);

    // ----- CSR build (once; reused by both layers) -----
    zero_cnt_kernel<<<nodeBlocks, 256>>>(Nn);
    hist_kernel<<<edgeBlocks, 256>>>(dstp, Ecnt);
    scan1_kernel<<<scanBlocks, 256>>>(Nn);
    scan2_kernel<<<1, 1024>>>(scanBlocks);
    scan3_kernel<<<(Nn + 256) / 256, 256>>>(Nn, Ecnt);
    scatter_kernel<<<edgeBlocks, 256>>>(srcp, dstp, et, ea, Ecnt, Nn);

    // ----- layer 1 -----
    gemm_xw_kernel<<<gemmGrid, 256>>>(x, 0, w1, Nn);
    nqnk_kernel<<<nqnkBlocks, 256>>>(x, 0, 0, Nn);
    {
        // fused agg writes into g_H; get its address via a tiny trampoline:
        // fused_agg writes through the pointer we pass; pass device-global g_H
        // via cudaGetSymbolAddress is host API (allowed, not allocation).
        void* hptr = nullptr;
        cudaGetSymbolAddress(&hptr, g_H);
        fused_agg_kernel<<<warpNodeBlk, 256>>>((float*)hptr, b1, 0, 1, Nn);
    }

    // ----- layer 2 -----
    gemm_xw_kernel<<<gemmGrid, 256>>>(x, 1, w2, Nn);
    nqnk_kernel<<<nqnkBlocks, 256>>>(x, 1, 1, Nn);
    fused_agg_kernel<<<warpNodeBlk, 256>>>(outp, b2, 1, 0, Nn);

    (void)g_H_ptr; (void)n_in; (void)out_size;
}

// round 5
// speedup vs baseline: 2.0936x; 1.1536x over previous
#include <cuda_runtime.h>
#include <cuda_bf16.h>
#include <cstdint>

#define RELS 3
#define F 128
#define NMAX 50000
#define EMAX 800000

// ---------------- scratch (static device globals; no allocation) ----------------
__device__ float g_XW[(size_t)RELS * NMAX * F];   // [r][n][f]  76.8 MB
__device__ float g_H[(size_t)NMAX * F];           // layer-1 output
__device__ float g_NQ[NMAX * RELS];
__device__ float g_NK[NMAX * RELS];
__device__ float g_EX[EMAX];
__device__ float g_WQ[2 * RELS * F];              // per-layer wq = w_r @ q
__device__ float g_WK[2 * RELS * F];
__device__ float g_CE[2];                         // per-layer scalar we . e
// CSR scratch
__device__ int   g_CNT[NMAX];
__device__ int   g_ROWPTR[NMAX + 1];
__device__ int   g_PART[NMAX];
__device__ int   g_BSUM[1024];
__device__ int   g_NKIDX[EMAX];                   // sorted: src*RELS + et
__device__ int   g_ROWIDX[EMAX];                  // sorted: et*Nn + src
__device__ float g_SEA[EMAX];                     // sorted: edge_attr

// ---------------- prep: wq/wk vectors + edge scalar ----------------
__global__ void prep_kernel(const float* __restrict__ w1, const float* __restrict__ q1,
                            const float* __restrict__ k1,
                            const float* __restrict__ w2, const float* __restrict__ q2,
                            const float* __restrict__ k2,
                            const float* __restrict__ we1, const float* __restrict__ e1,
                            const float* __restrict__ we2, const float* __restrict__ e2) {
    int idx = blockIdx.x * blockDim.x + threadIdx.x;
    if (idx < 4 * RELS * F) {
        int which = idx / (RELS * F);
        int rem   = idx % (RELS * F);
        const float* w = (which < 2) ? w1 : w2;
        const float* v = (which == 0) ? q1 : (which == 1) ? k1 : (which == 2) ? q2 : k2;
        const float* row = w + (size_t)rem * F;
        float s = 0.f;
        #pragma unroll 8
        for (int o = 0; o < F; o++) s += row[o] * v[o];
        float* d = (which == 0) ? g_WQ
                 : (which == 1) ? g_WK
                 : (which == 2) ? (g_WQ + RELS * F)
                 : (g_WK + RELS * F);
        d[rem] = s;
    } else if (idx == 4 * RELS * F) {
        float s = 0.f;
        for (int o = 0; o < F; o++) s += we1[o] * e1[o];
        g_CE[0] = s;
    } else if (idx == 4 * RELS * F + 1) {
        float s = 0.f;
        for (int o = 0; o < F; o++) s += we2[o] * e2[o];
        g_CE[1] = s;
    }
}

// ---------------- CSR build ----------------
__global__ void zero_cnt_kernel(int Nn) {
    int i = blockIdx.x * blockDim.x + threadIdx.x;
    if (i < Nn) g_CNT[i] = 0;
}
__global__ void hist_kernel(const int* __restrict__ dst, int Ecnt) {
    int e = blockIdx.x * blockDim.x + threadIdx.x;
    if (e < Ecnt) atomicAdd(&g_CNT[dst[e]], 1);
}
__global__ void scan1_kernel(int Nn) {
    __shared__ int sh[256];
    int i = blockIdx.x * 256 + threadIdx.x;
    int v = (i < Nn) ? g_CNT[i] : 0;
    sh[threadIdx.x] = v;
    __syncthreads();
    #pragma unroll
    for (int off = 1; off < 256; off <<= 1) {
        int t = (threadIdx.x >= off) ? sh[threadIdx.x - off] : 0;
        __syncthreads();
        sh[threadIdx.x] += t;
        __syncthreads();
    }
    if (i < Nn) g_PART[i] = sh[threadIdx.x] - v;
    if (threadIdx.x == 255) g_BSUM[blockIdx.x] = sh[255];
}
__global__ void scan2_kernel(int nb) {
    __shared__ int sh[1024];
    int v = (threadIdx.x < nb) ? g_BSUM[threadIdx.x] : 0;
    sh[threadIdx.x] = v;
    __syncthreads();
    #pragma unroll
    for (int off = 1; off < 1024; off <<= 1) {
        int t = (threadIdx.x >= off) ? sh[threadIdx.x - off] : 0;
        __syncthreads();
        sh[threadIdx.x] += t;
        __syncthreads();
    }
    if (threadIdx.x < nb) g_BSUM[threadIdx.x] = sh[threadIdx.x] - v;
}
__global__ void scan3_kernel(int Nn, int Ecnt) {
    int i = blockIdx.x * blockDim.x + threadIdx.x;
    if (i < Nn) {
        g_ROWPTR[i] = g_PART[i] + g_BSUM[i >> 8];
        g_CNT[i] = 0;
    }
    if (i == Nn) g_ROWPTR[Nn] = Ecnt;
}
__global__ void scatter_kernel(const int* __restrict__ src, const int* __restrict__ dst,
                               const int* __restrict__ et, const float* __restrict__ ea,
                               int Ecnt, int Nn) {
    int e = blockIdx.x * blockDim.x + threadIdx.x;
    if (e >= Ecnt) return;
    int d = dst[e];
    int pos = g_ROWPTR[d] + atomicAdd(&g_CNT[d], 1);
    int s = src[e], t = et[e];
    g_NKIDX[pos]  = s * RELS + t;
    g_ROWIDX[pos] = t * Nn + s;
    g_SEA[pos]    = ea[e];
}

// ============== mma.sync bf16 GEMM with 2-term split: XW[r] = X @ W_r ==============
// Smem tiles stored as 32-bit bf16-pairs with row pitch 68 words (64 data + 4 pad)
// so fragment loads hit banks (4g + tig) % 32 -> conflict-free.
#define APITCH 68
#define TILE_WORDS (128 * APITCH)                 // words per tile
#define GEMM_SMEM_TOTAL (4 * TILE_WORDS * 4)      // A_hi, A_lo, B_hi, B_lo (bytes)

__device__ __forceinline__ uint32_t pack_split_hi(float x, float y) {
    __nv_bfloat16 hx = __float2bfloat16_rn(x);
    __nv_bfloat16 hy = __float2bfloat16_rn(y);
    return ((uint32_t)*(uint16_t*)&hy << 16) | (uint32_t)*(uint16_t*)&hx;
}
__device__ __forceinline__ uint32_t pack_split_lo(float x, float y) {
    __nv_bfloat16 hx = __float2bfloat16_rn(x);
    __nv_bfloat16 hy = __float2bfloat16_rn(y);
    __nv_bfloat16 lx = __float2bfloat16_rn(x - __bfloat162float(hx));
    __nv_bfloat16 ly = __float2bfloat16_rn(y - __bfloat162float(hy));
    return ((uint32_t)*(uint16_t*)&ly << 16) | (uint32_t)*(uint16_t*)&lx;
}

__device__ __forceinline__ void mma16816(float* d, const uint32_t* a, const uint32_t* b) {
    asm volatile("mma.sync.aligned.m16n8k16.row.col.f32.bf16.bf16.f32 "
                 "{%0,%1,%2,%3}, {%4,%5,%6,%7}, {%8,%9}, {%0,%1,%2,%3};"
                 : "+f"(d[0]), "+f"(d[1]), "+f"(d[2]), "+f"(d[3])
                 : "r"(a[0]), "r"(a[1]), "r"(a[2]), "r"(a[3]), "r"(b[0]), "r"(b[1]));
}

__global__ __launch_bounds__(256) void gemm_mma_kernel(const float* __restrict__ xin,
                                                       int use_h,
                                                       const float* __restrict__ W,
                                                       int Nn) {
    extern __shared__ uint32_t smem[];
    uint32_t* sAhi = smem;
    uint32_t* sAlo = smem + TILE_WORDS;
    uint32_t* sBhi = smem + 2 * TILE_WORDS;
    uint32_t* sBlo = smem + 3 * TILE_WORDS;

    const float* X = use_h ? g_H : xin;
    int r = blockIdx.y;
    const float* Wr = W + (size_t)r * F * F;
    float* outp = g_XW + (size_t)r * Nn * F;
    int rowBase = blockIdx.x * 128;

    int tid = threadIdx.x;

    // ---- A tile: X rows rowBase..+127 as [row][kpair], hi/lo split ----
    for (int idx = tid; idx < 128 * 64; idx += 256) {
        int row = idx >> 6;
        int pair = idx & 63;
        int grow = rowBase + row;
        float2 v = make_float2(0.f, 0.f);
        if (grow < Nn) v = *(const float2*)(X + (size_t)grow * F + pair * 2);
        sAhi[row * APITCH + pair] = pack_split_hi(v.x, v.y);
        sAlo[row * APITCH + pair] = pack_split_lo(v.x, v.y);
    }
    // ---- B tile: B[n][k] = W[k][n] (transpose on load), hi/lo split ----
    for (int idx = tid; idx < 64 * 128; idx += 256) {
        int p = idx >> 7;          // k-pair
        int o = idx & 127;         // n
        float vx = Wr[(size_t)(2 * p) * F + o];
        float vy = Wr[(size_t)(2 * p + 1) * F + o];
        sBhi[o * APITCH + p] = pack_split_hi(vx, vy);
        sBlo[o * APITCH + p] = pack_split_lo(vx, vy);
    }
    __syncthreads();

    // ---- compute: warp (wid&3) rows 32, (wid>>2) cols 64 ----
    int wid = tid >> 5;
    int lane = tid & 31;
    int warpM = wid & 3;
    int warpN = wid >> 2;
    int g = lane >> 2;             // group 0..7
    int tig = lane & 3;            // thread-in-group

    float acc[2][8][4];
    #pragma unroll
    for (int mt = 0; mt < 2; mt++)
        #pragma unroll
        for (int nt = 0; nt < 8; nt++)
            #pragma unroll
            for (int c = 0; c < 4; c++) acc[mt][nt][c] = 0.f;

    #pragma unroll
    for (int split = 0; split < 3; split++) {
        const uint32_t* As = (split == 2) ? sAlo : sAhi;
        const uint32_t* Bs = (split == 1) ? sBlo : sBhi;
        #pragma unroll
        for (int ks = 0; ks < 8; ks++) {
            int kp = ks * 8 + tig;       // k-pair base for this thread
            uint32_t a[2][4];
            #pragma unroll
            for (int mt = 0; mt < 2; mt++) {
                int row = warpM * 32 + mt * 16;
                a[mt][0] = As[(row + g) * APITCH + kp];
                a[mt][1] = As[(row + g + 8) * APITCH + kp];
                a[mt][2] = As[(row + g) * APITCH + kp + 4];
                a[mt][3] = As[(row + g + 8) * APITCH + kp + 4];
            }
            uint32_t b[8][2];
            #pragma unroll
            for (int nt = 0; nt < 8; nt++) {
                int n = warpN * 64 + nt * 8 + g;
                b[nt][0] = Bs[n * APITCH + kp];
                b[nt][1] = Bs[n * APITCH + kp + 4];
            }
            #pragma unroll
            for (int mt = 0; mt < 2; mt++)
                #pragma unroll
                for (int nt = 0; nt < 8; nt++)
                    mma16816(acc[mt][nt], a[mt], b[nt]);
        }
    }

    // ---- epilogue: direct global stores (float2 per fragment row) ----
    #pragma unroll
    for (int mt = 0; mt < 2; mt++) {
        int row0 = rowBase + warpM * 32 + mt * 16 + g;
        int row1 = row0 + 8;
        #pragma unroll
        for (int nt = 0; nt < 8; nt++) {
            int col = warpN * 64 + nt * 8 + tig * 2;
            if (row0 < Nn)
                *(float2*)(outp + (size_t)row0 * F + col) = make_float2(acc[mt][nt][0], acc[mt][nt][1]);
            if (row1 < Nn)
                *(float2*)(outp + (size_t)row1 * F + col) = make_float2(acc[mt][nt][2], acc[mt][nt][3]);
        }
    }
}

// ---------------- per-node attention logits ----------------
__global__ __launch_bounds__(256) void nqnk_kernel(const float* __restrict__ xin,
                                                   int use_h, int layer, int Nn) {
    __shared__ float swq[RELS * F];
    __shared__ float swk[RELS * F];
    const float* X = use_h ? g_H : xin;
    const float* WQ = g_WQ + layer * RELS * F;
    const float* WK = g_WK + layer * RELS * F;
    for (int i = threadIdx.x; i < RELS * F; i += blockDim.x) {
        swq[i] = WQ[i];
        swk[i] = WK[i];
    }
    __syncthreads();

    int warp = (blockIdx.x * blockDim.x + threadIdx.x) >> 5;
    int lane = threadIdx.x & 31;
    if (warp >= Nn) return;

    const float* xr = X + (size_t)warp * F;
    float x0 = xr[lane], x1 = xr[lane + 32], x2 = xr[lane + 64], x3 = xr[lane + 96];

    #pragma unroll
    for (int r = 0; r < RELS; r++) {
        const float* wq = swq + r * F;
        const float* wk = swk + r * F;
        float sq = x0 * wq[lane] + x1 * wq[lane + 32] + x2 * wq[lane + 64] + x3 * wq[lane + 96];
        float sk = x0 * wk[lane] + x1 * wk[lane + 32] + x2 * wk[lane + 64] + x3 * wk[lane + 96];
        #pragma unroll
        for (int off = 16; off; off >>= 1) {
            sq += __shfl_down_sync(0xffffffffu, sq, off);
            sk += __shfl_down_sync(0xffffffffu, sk, off);
        }
        if (lane == 0) {
            g_NQ[warp * RELS + r] = sq;
            g_NK[warp * RELS + r] = sk;
        }
    }
}

// ---------------- fused softmax + aggregate + bias(+relu), warp per dst node ----------------
__global__ __launch_bounds__(256) void fused_agg_kernel(float* __restrict__ outp,
                                                        const float* __restrict__ bias,
                                                        int layer, int relu, int Nn) {
    int node = (blockIdx.x * blockDim.x + threadIdx.x) >> 5;
    int lane = threadIdx.x & 31;
    if (node >= Nn) return;

    int start = g_ROWPTR[node];
    int end   = g_ROWPTR[node + 1];
    float ce  = g_CE[layer];
    float nq0 = g_NQ[node * RELS + 0];
    float nq1 = g_NQ[node * RELS + 1];
    float nq2 = g_NQ[node * RELS + 2];

    float denom = 0.f;
    for (int i = start + lane; i < end; i += 32) {
        int nkidx = g_NKIDX[i];
        int t = nkidx - (nkidx / RELS) * RELS;
        float nq = (t == 0) ? nq0 : (t == 1) ? nq1 : nq2;
        float a = nq + g_NK[nkidx] + ce * g_SEA[i];
        a = (a > 0.f) ? a : 0.2f * a;
        float ex = expf(a);
        g_EX[i] = ex;
        denom += ex;
    }
    #pragma unroll
    for (int off = 16; off; off >>= 1)
        denom += __shfl_xor_sync(0xffffffffu, denom, off);
    float inv = 1.f / (denom + 1e-16f);

    float4 acc = make_float4(0.f, 0.f, 0.f, 0.f);
    int i = start;
    for (; i + 1 < end; i += 2) {
        float at0 = g_EX[i] * inv;
        float at1 = g_EX[i + 1] * inv;
        const float4* r0 = (const float4*)(g_XW + (size_t)g_ROWIDX[i] * F);
        const float4* r1 = (const float4*)(g_XW + (size_t)g_ROWIDX[i + 1] * F);
        float4 v0 = r0[lane];
        float4 v1 = r1[lane];
        acc.x += at0 * v0.x + at1 * v1.x;
        acc.y += at0 * v0.y + at1 * v1.y;
        acc.z += at0 * v0.z + at1 * v1.z;
        acc.w += at0 * v0.w + at1 * v1.w;
    }
    if (i < end) {
        float at = g_EX[i] * inv;
        const float4* r0 = (const float4*)(g_XW + (size_t)g_ROWIDX[i] * F);
        float4 v = r0[lane];
        acc.x += at * v.x;
        acc.y += at * v.y;
        acc.z += at * v.z;
        acc.w += at * v.w;
    }

    const float4 b = *(const float4*)(bias + lane * 4);
    acc.x += b.x; acc.y += b.y; acc.z += b.z; acc.w += b.w;
    if (relu) {
        acc.x = acc.x > 0.f ? acc.x : 0.f;
        acc.y = acc.y > 0.f ? acc.y : 0.f;
        acc.z = acc.z > 0.f ? acc.z : 0.f;
        acc.w = acc.w > 0.f ? acc.w : 0.f;
    }
    *(float4*)(outp + (size_t)node * F + lane * 4) = acc;
}

// ---------------- launch ----------------
extern "C" void kernel_launch(void* const* d_in, const int* in_sizes, int n_in,
                              void* d_out, int out_size) {
    const float* x   = (const float*)d_in[0];
    const int*   ei  = (const int*)d_in[1];
    const int*   et  = (const int*)d_in[2];
    const float* ea  = (const float*)d_in[3];
    const float* w1  = (const float*)d_in[4];
    const float* q1  = (const float*)d_in[5];
    const float* k1  = (const float*)d_in[6];
    const float* e1  = (const float*)d_in[7];
    const float* we1 = (const float*)d_in[8];
    const float* b1  = (const float*)d_in[9];
    const float* w2  = (const float*)d_in[10];
    const float* q2  = (const float*)d_in[11];
    const float* k2  = (const float*)d_in[12];
    const float* e2  = (const float*)d_in[13];
    const float* we2 = (const float*)d_in[14];
    const float* b2  = (const float*)d_in[15];

    int Nn = in_sizes[0] / F;
    int Ecnt = in_sizes[2];
    const int* srcp = ei;
    const int* dstp = ei + Ecnt;
    float* outp = (float*)d_out;

    int nodeBlocks  = (Nn + 255) / 256;
    int edgeBlocks  = (Ecnt + 255) / 256;
    int scanBlocks  = (Nn + 255) / 256;
    dim3 gemmGrid((Nn + 127) / 128, RELS);
    int nqnkBlocks  = (Nn + 7) / 8;
    int warpNodeBlk = (Nn + 7) / 8;

    cudaFuncSetAttribute(gemm_mma_kernel, cudaFuncAttributeMaxDynamicSharedMemorySize,
                         GEMM_SMEM_TOTAL);

    prep_kernel<<<(4 * RELS * F + 2 + 255) / 256, 256>>>(w1, q1, k1, w2, q2, k2,
                                                         we1, e1, we2, e2);

    // ----- CSR build (once; reused by both layers) -----
    zero_cnt_kernel<<<nodeBlocks, 256>>>(Nn);
    hist_kernel<<<edgeBlocks, 256>>>(dstp, Ecnt);
    scan1_kernel<<<scanBlocks, 256>>>(Nn);
    scan2_kernel<<<1, 1024>>>(scanBlocks);
    scan3_kernel<<<(Nn + 256) / 256, 256>>>(Nn, Ecnt);
    scatter_kernel<<<edgeBlocks, 256>>>(srcp, dstp, et, ea, Ecnt, Nn);

    void* hptr = nullptr;
    cudaGetSymbolAddress(&hptr, g_H);

    // ----- layer 1 -----
    gemm_mma_kernel<<<gemmGrid, 256, GEMM_SMEM_TOTAL>>>(x, 0, w1, Nn);
    nqnk_kernel<<<nqnkBlocks, 256>>>(x, 0, 0, Nn);
    fused_agg_kernel<<<warpNodeBlk, 256>>>((float*)hptr, b1, 0, 1, Nn);

    // ----- layer 2 -----
    gemm_mma_kernel<<<gemmGrid, 256, GEMM_SMEM_TOTAL>>>(x, 1, w2, Nn);
    nqnk_kernel<<<nqnkBlocks, 256>>>(x, 1, 1, Nn);
    fused_agg_kernel<<<warpNodeBlk, 256>>>(outp, b2, 1, 0, Nn);

    (void)n_in; (void)out_size;
}